// round 16
// baseline (speedup 1.0000x reference)
#include <cuda_runtime.h>
#include <cuda_fp16.h>
#include <cstdint>

// Fused masked SDPA, both GEMMs via mma.sync fp16 (baseline PTX, compute_103).
// 128-thread CTAs, BQ=128: each warp owns TWO m16 q-groups (32 q-rows) so
// every ldsm'd K/V fragment feeds 4 mma (2x arithmetic intensity).
// Q lives in smem as fp16 (pre-scaled); A-frags via ldmatrix -> low reg use.
// GEMM2: P(fp16 regs, == S D-frag layout, no shuffles) x V^T(fp16 smem).
// Pre-passes: Q -> g_Qc (fp16*scale), K -> g_Kc (fp16), V -> g_Vt (fp16, T).
// NOTE: pre-pass dst selected INSIDE the kernel (host code must not take the
// address of __device__ globals -- that was the R12 correctness bug).
// sched: LPT batch order. Persistent CTAs, cp.async double-buffered tiles.

#define DD    128
#define BQ    128
#define BK    64
#define NTH   128
#define QSTRB 272                       // Q smem row stride (bytes)
#define KSTRB 272                       // K smem row stride (bytes)
#define VSTRB 144                       // V^T smem row stride (bytes)
#define QOFFB 0
#define QSZB  (BQ * QSTRB)              // 34816
#define BUF0B QSZB                      // tile buffers after Q
#define VOFFB (BK * KSTRB)              // 17408 within a buffer
#define BUFB  (VOFFB + DD * VSTRB)      // 35840 per buffer
#define SMEMB (QSZB + 2 * BUFB + 16)    // 106512
#define WSLOT ((QSZB + 2 * BUFB) / 4)

__device__ __half g_Vt[16ull * 128ull * 4096ull];  // [B][d][key] fp16
__device__ __half g_Kc[16ull * 4096ull * 128ull];  // [B][key][d] fp16
__device__ __half g_Qc[16ull * 4096ull * 128ull];  // [B][q][d] fp16 * scale
__device__ int    g_next;
__device__ int    g_order[64];

__device__ __forceinline__ uint32_t smem_u32(const void* p) {
    uint32_t a;
    asm("{ .reg .u64 t; cvta.to.shared.u64 t, %1; cvt.u32.u64 %0, t; }"
        : "=r"(a) : "l"(p));
    return a;
}

__device__ __forceinline__ void ldsm4(uint32_t* r, uint32_t addr) {
    asm volatile("ldmatrix.sync.aligned.m8n8.x4.shared.b16 {%0,%1,%2,%3}, [%4];"
                 : "=r"(r[0]), "=r"(r[1]), "=r"(r[2]), "=r"(r[3]) : "r"(addr));
}

__device__ __forceinline__ void mma16h(float* d, const uint32_t* a,
                                       uint32_t b0, uint32_t b1) {
    asm volatile(
        "mma.sync.aligned.m16n8k16.row.col.f32.f16.f16.f32 "
        "{%0,%1,%2,%3}, {%4,%5,%6,%7}, {%8,%9}, {%0,%1,%2,%3};"
        : "+f"(d[0]), "+f"(d[1]), "+f"(d[2]), "+f"(d[3])
        : "r"(a[0]), "r"(a[1]), "r"(a[2]), "r"(a[3]), "r"(b0), "r"(b1));
}

__device__ __forceinline__ void cpa16(uint32_t dst, const void* src) {
    asm volatile("cp.async.cg.shared.global [%0], [%1], 16;"
                 :: "r"(dst), "l"(src) : "memory");
}
#define CPA_COMMIT() asm volatile("cp.async.commit_group;" ::: "memory")
#define CPA_WAIT(n)  asm volatile("cp.async.wait_group %0;" :: "n"(n) : "memory")

// ---------------- pre-pass: fp32 -> fp16 copy into g_Kc or g_Qc ----------------
__global__ void hconv(const float* __restrict__ src, float scl, int which,
                      size_t n4) {
    __half* dst = which ? g_Qc : g_Kc;      // device-side symbol resolution
    size_t i = (size_t)blockIdx.x * blockDim.x + threadIdx.x;
    if (i < n4) {
        float4 v = ((const float4*)src)[i];
        __half2 h0 = __floats2half2_rn(v.x * scl, v.y * scl);
        __half2 h1 = __floats2half2_rn(v.z * scl, v.w * scl);
        ((uint2*)dst)[i] = make_uint2(*(uint32_t*)&h0, *(uint32_t*)&h1);
    }
}

// ---------------- pre-pass: V -> g_Vt[b][d][key] (fp16) ----------------
__global__ void vtrans(const float* __restrict__ Vg, int Kn) {
    __shared__ float tile[32][33];
    const int b  = blockIdx.z;
    const int k0 = blockIdx.x * 32;
    const int d0 = blockIdx.y * 32;
    const int tx = threadIdx.x, ty = threadIdx.y;

    const float* src = Vg + ((size_t)b * Kn + k0) * DD + d0;
    #pragma unroll
    for (int j = 0; j < 4; j++)
        tile[ty + 8 * j][tx] = src[(size_t)(ty + 8 * j) * DD + tx];
    __syncthreads();

    __half* dst = g_Vt + ((size_t)b * DD + d0) * Kn + k0;
    #pragma unroll
    for (int j = 0; j < 4; j++)
        dst[(size_t)(ty + 8 * j) * Kn + tx] = __float2half_rn(tile[tx][ty + 8 * j]);
}

// ---------------- scheduler: LPT batch order + counter reset ----------------
__global__ void sched(const int* __restrict__ vlen, int B) {
    if (threadIdx.x == 0) {
        int idx[64], vl[64];
        for (int i = 0; i < B; i++) { idx[i] = i; vl[i] = vlen[i]; }
        for (int i = 1; i < B; i++) {           // insertion sort desc, stable
            int vi = vl[i], ii = idx[i], j = i - 1;
            while (j >= 0 && vl[j] < vi) {
                vl[j + 1] = vl[j]; idx[j + 1] = idx[j]; j--;
            }
            vl[j + 1] = vi; idx[j + 1] = ii;
        }
        for (int i = 0; i < B; i++) g_order[i] = idx[i];
        g_next = 0;
    }
}

// ---------------- main fused attention (persistent, 2 CTAs/SM) ----------------
__global__ __launch_bounds__(NTH, 2)
void attn_mma(const int* __restrict__ vlen, float* __restrict__ Og,
              int Qn, int Kn, int nq, int nunits)
{
    extern __shared__ uint32_t smem[];
    const uint32_t sbase = smem_u32(smem);

    const int tid  = threadIdx.x;
    const int w    = tid >> 5;                  // 0..3
    const int lane = tid & 31;
    const int g    = lane >> 2;                 // row within m16 group
    const int t    = lane & 3;                  // thread-in-group
    const unsigned FULL = 0xFFFFFFFFu;

    // B-operand ldmatrix lane pattern (K and V^T):
    //   m0=(rows0-7,ch0) m1=(rows0-7,ch1) m2=(rows8-15,ch0) m3=(rows8-15,ch1)
    const int rlyB = (lane & 7) + ((lane >> 4) & 1) * 8;
    const int ccB  = (lane >> 3) & 1;
    const uint32_t kB0 = sbase + BUF0B + (uint32_t)(rlyB * KSTRB + ccB * 16);
    const uint32_t vB0 = sbase + BUF0B + VOFFB + (uint32_t)(rlyB * VSTRB + ccB * 16);

    // A-operand ldmatrix lane pattern (Q):
    //   m0=(rows0-7,ch0) m1=(rows8-15,ch0) m2=(rows0-7,ch1) m3=(rows8-15,ch1)
    const int rlyA = (lane & 7) + ((lane >> 3) & 1) * 8;
    const int ccA  = (lane >> 4) & 1;
    const uint32_t qA0 = sbase + QOFFB + (uint32_t)((w * 16 + rlyA) * QSTRB + ccA * 16);
    const uint32_t qA1 = qA0 + (uint32_t)(64 * QSTRB);

    // cp.async per-thread address components (loop-invariant)
    const int ldK_r = tid >> 4, ldK_c = (tid & 15) * 16;   // K: 8 steps of 8 rows
    const int ldV_d = tid >> 3, ldV_k = (tid & 7) * 16;    // V: 8 steps of 16 rows
    const int ldQ_r = tid >> 4, ldQ_c = (tid & 15) * 16;   // Q: 16 steps of 8 rows

    for (;;) {
        // ---- pop next work unit ----
        if (tid == 0) smem[WSLOT] = (uint32_t)atomicAdd(&g_next, 1);
        __syncthreads();
        const int u = (int)smem[WSLOT];
        if (u >= nunits) break;

        const int b     = g_order[u / nq];
        const int q0    = (u % nq) * BQ;
        const int valid = vlen[b];

        const __half* kcb = g_Kc + (size_t)b * Kn * DD;
        const __half* vtb = g_Vt + (size_t)b * DD * Kn;
        const __half* qcb = g_Qc + ((size_t)b * Qn + q0) * DD;

        // ---- stage Q tile into smem (fp16, pre-scaled) via cp.async ----
        {
            uint32_t qdst = sbase + QOFFB + (uint32_t)(ldQ_r * QSTRB + ldQ_c);
            const __half* qsrc = qcb + (size_t)ldQ_r * DD + (ldQ_c >> 1);
            #pragma unroll
            for (int c = 0; c < 16; c++)
                cpa16(qdst + (uint32_t)(c * 8 * QSTRB), qsrc + (size_t)(c * 8) * DD);
            CPA_COMMIT();
        }

        float oacc[2][16][4];
        #pragma unroll
        for (int gr = 0; gr < 2; gr++)
            #pragma unroll
            for (int i = 0; i < 16; i++)
                { oacc[gr][i][0] = oacc[gr][i][1] = oacc[gr][i][2] = oacc[gr][i][3] = 0.f; }
        float lacc[2][2] = {{0.f, 0.f}, {0.f, 0.f}};

        const int ktiles = (valid + BK - 1) / BK;

        auto load_tile = [&](int kt, uint32_t bb) {
            const int k0 = kt * BK;
            const __half* ksrc = kcb + (size_t)(k0 + ldK_r) * DD + (ldK_c >> 1);
            uint32_t kdst = sbase + BUF0B + bb + (uint32_t)(ldK_r * KSTRB + ldK_c);
            #pragma unroll
            for (int c = 0; c < 8; c++)
                cpa16(kdst + (uint32_t)(c * 8 * KSTRB), ksrc + (size_t)(c * 8) * DD);
            const __half* vsrc = vtb + (size_t)ldV_d * Kn + k0 + (ldV_k >> 1);
            uint32_t vdst = sbase + BUF0B + bb + VOFFB + (uint32_t)(ldV_d * VSTRB + ldV_k);
            #pragma unroll
            for (int c = 0; c < 8; c++)
                cpa16(vdst + (uint32_t)(c * 16 * VSTRB), vsrc + (size_t)(c * 16) * Kn);
        };

        auto step = [&](int kt, uint32_t boff, uint32_t obff) {
            const int k0 = kt * BK;
            if (kt + 1 < ktiles) {
                load_tile(kt + 1, obff);
                CPA_COMMIT();
                CPA_WAIT(1);
            } else {
                CPA_WAIT(0);
            }
            __syncthreads();

            // ---- GEMM1: S(32x64) = Q . K^T; each K frag feeds both groups ----
            float sacc[2][8][4];
            #pragma unroll
            for (int gr = 0; gr < 2; gr++)
                #pragma unroll
                for (int i = 0; i < 8; i++)
                    { sacc[gr][i][0] = sacc[gr][i][1] = sacc[gr][i][2] = sacc[gr][i][3] = 0.f; }

            #pragma unroll
            for (int c = 0; c < 8; c++) {            // k16 chunk over d
                uint32_t qa0[4], qa1[4];
                ldsm4(qa0, qA0 + (uint32_t)(c * 32));
                ldsm4(qa1, qA1 + (uint32_t)(c * 32));
                #pragma unroll
                for (int ng = 0; ng < 4; ng++) {     // n16 group over keys
                    uint32_t kb[4];
                    ldsm4(kb, kB0 + boff + (uint32_t)(ng * 16 * KSTRB + c * 32));
                    mma16h(sacc[0][2 * ng],     qa0, kb[0], kb[1]);
                    mma16h(sacc[0][2 * ng + 1], qa0, kb[2], kb[3]);
                    mma16h(sacc[1][2 * ng],     qa1, kb[0], kb[1]);
                    mma16h(sacc[1][2 * ng + 1], qa1, kb[2], kb[3]);
                }
            }

            // ---- mask + exp + row-sums; pack P to fp16 (== A-frag layout) ----
            uint32_t ph[2][8][2];
            #pragma unroll
            for (int gr = 0; gr < 2; gr++) {
                #pragma unroll
                for (int nb = 0; nb < 8; nb++) {
                    const int c0 = k0 + nb * 8 + 2 * t;
                    const bool m0 = c0 < valid, m1 = (c0 + 1) < valid;
                    float p0 = m0 ? __expf(sacc[gr][nb][0]) : 0.f;
                    float p1 = m1 ? __expf(sacc[gr][nb][1]) : 0.f;
                    float p2 = m0 ? __expf(sacc[gr][nb][2]) : 0.f;
                    float p3 = m1 ? __expf(sacc[gr][nb][3]) : 0.f;
                    lacc[gr][0] += p0 + p1;  lacc[gr][1] += p2 + p3;
                    __half2 h0 = __floats2half2_rn(p0, p1);
                    __half2 h1 = __floats2half2_rn(p2, p3);
                    ph[gr][nb][0] = *(uint32_t*)&h0;
                    ph[gr][nb][1] = *(uint32_t*)&h1;
                }
            }

            // ---- GEMM2: O(32x128) += P . V; each V frag feeds both groups ----
            #pragma unroll
            for (int i = 0; i < 4; i++) {            // k16 chunk over 64 keys
                uint32_t a0[4], a1[4];
                a0[0] = ph[0][2 * i][0];  a0[1] = ph[0][2 * i][1];
                a0[2] = ph[0][2 * i + 1][0]; a0[3] = ph[0][2 * i + 1][1];
                a1[0] = ph[1][2 * i][0];  a1[1] = ph[1][2 * i][1];
                a1[2] = ph[1][2 * i + 1][0]; a1[3] = ph[1][2 * i + 1][1];
                #pragma unroll
                for (int nbp = 0; nbp < 8; nbp++) {  // n16 block over d
                    uint32_t vb[4];
                    ldsm4(vb, vB0 + boff + (uint32_t)(nbp * 16 * VSTRB + i * 32));
                    mma16h(oacc[0][2 * nbp],     a0, vb[0], vb[1]);
                    mma16h(oacc[0][2 * nbp + 1], a0, vb[2], vb[3]);
                    mma16h(oacc[1][2 * nbp],     a1, vb[0], vb[1]);
                    mma16h(oacc[1][2 * nbp + 1], a1, vb[2], vb[3]);
                }
            }

            __syncthreads();    // buffer reusable before next-next cp.async
        };

        load_tile(0, 0u);
        CPA_COMMIT();

        for (int kt = 0; kt < ktiles; kt += 2) {
            step(kt, 0u, (uint32_t)BUFB);                     // buffer 0
            if (kt + 1 < ktiles)
                step(kt + 1, (uint32_t)BUFB, 0u);             // buffer 1
        }

        // ---- epilogue: reduce row sums in quad, normalize, store ----
        #pragma unroll
        for (int gr = 0; gr < 2; gr++) {
            float l0 = lacc[gr][0], l1 = lacc[gr][1];
            l0 += __shfl_xor_sync(FULL, l0, 1);
            l0 += __shfl_xor_sync(FULL, l0, 2);
            l1 += __shfl_xor_sync(FULL, l1, 1);
            l1 += __shfl_xor_sync(FULL, l1, 2);
            const float inv0 = 1.0f / l0;
            const float inv1 = 1.0f / l1;

            const int rbase = q0 + gr * 64 + w * 16;
            float2* o0 = (float2*)(Og + ((size_t)b * Qn + rbase + g) * DD);
            float2* o1 = (float2*)(Og + ((size_t)b * Qn + rbase + g + 8) * DD);
            #pragma unroll
            for (int nb = 0; nb < 16; nb++) {
                o0[nb * 4 + t] = make_float2(oacc[gr][nb][0] * inv0,
                                             oacc[gr][nb][1] * inv0);
                o1[nb * 4 + t] = make_float2(oacc[gr][nb][2] * inv1,
                                             oacc[gr][nb][3] * inv1);
            }
        }
    }
}

extern "C" void kernel_launch(void* const* d_in, const int* in_sizes, int n_in,
                              void* d_out, int out_size)
{
    const float* Q  = (const float*)d_in[0];
    const float* K  = (const float*)d_in[1];
    const float* V  = (const float*)d_in[2];
    const int*   vl = (const int*)d_in[3];

    const int B  = in_sizes[3];
    const int Qn = in_sizes[0] / (B * DD);
    const int Kn = in_sizes[1] / (B * DD);
    const int nq = Qn / BQ;
    const int nunits = B * nq;

    const float scale = 0.088388347648318447f;   // 1/sqrt(128)
    const size_t nk4 = (size_t)B * Kn * DD / 4;
    const size_t nq4 = (size_t)B * Qn * DD / 4;
    hconv<<<(unsigned)((nk4 + 255) / 256), 256>>>(K, 1.0f, 0, nk4);
    hconv<<<(unsigned)((nq4 + 255) / 256), 256>>>(Q, scale, 1, nq4);

    dim3 tg(Kn / 32, DD / 32, B);
    vtrans<<<tg, dim3(32, 8)>>>(V, Kn);

    sched<<<1, 32>>>(vl, B);

    int dev = 0, nsm = 148;
    cudaGetDevice(&dev);
    cudaDeviceGetAttribute(&nsm, cudaDevAttrMultiProcessorCount, dev);
    int grid = 2 * nsm;
    if (grid > nunits) grid = nunits;

    cudaFuncSetAttribute(attn_mma, cudaFuncAttributeMaxDynamicSharedMemorySize,
                         SMEMB);
    attn_mma<<<grid, NTH, SMEMB>>>(vl, (float*)d_out, Qn, Kn, nq, nunits);
}

// round 17
// speedup vs baseline: 1.0822x; 1.0822x over previous
#include <cuda_runtime.h>
#include <cuda_fp16.h>
#include <cstdint>

// Fused masked SDPA, both GEMMs via mma.sync fp16 (baseline PTX, compute_103).
// Mainloop = R11 best-known: 128-thr CTAs (BQ=64), 3 CTAs/SM (170-reg cap),
// tile loop unrolled x2 with literal buffer offsets, cp.async double-buffered.
// R17: fast sched (parallel vlen load), masked-aware pre-passes (skip keys
// beyond ceil(valid/64)*64 in K-conv and V-transpose).

#define DD    128
#define BQ    64
#define BK    64
#define NTH   128
#define KSTRB 272                       // K smem row stride (bytes, 136 halfs)
#define VSTRB 144                       // V^T smem row stride (bytes, 72 halfs)
#define VOFFB (BK * KSTRB)              // 17408: V^T offset within buffer
#define BUFB  (VOFFB + DD * VSTRB)      // 35840 B per buffer
#define SMEMB (2 * BUFB + 16)
#define WSLOT (2 * BUFB / 4)

__device__ __half g_Vt[16ull * 128ull * 4096ull];  // [B][d][key] fp16
__device__ __half g_Kc[16ull * 4096ull * 128ull];  // [B][key][d] fp16
__device__ int    g_next;
__device__ int    g_order[64];

__device__ __forceinline__ uint32_t smem_u32(const void* p) {
    uint32_t a;
    asm("{ .reg .u64 t; cvta.to.shared.u64 t, %1; cvt.u32.u64 %0, t; }"
        : "=r"(a) : "l"(p));
    return a;
}

__device__ __forceinline__ void ldsm4(uint32_t* r, uint32_t addr) {
    asm volatile("ldmatrix.sync.aligned.m8n8.x4.shared.b16 {%0,%1,%2,%3}, [%4];"
                 : "=r"(r[0]), "=r"(r[1]), "=r"(r[2]), "=r"(r[3]) : "r"(addr));
}

__device__ __forceinline__ void mma16h(float* d, const uint32_t* a,
                                       uint32_t b0, uint32_t b1) {
    asm volatile(
        "mma.sync.aligned.m16n8k16.row.col.f32.f16.f16.f32 "
        "{%0,%1,%2,%3}, {%4,%5,%6,%7}, {%8,%9}, {%0,%1,%2,%3};"
        : "+f"(d[0]), "+f"(d[1]), "+f"(d[2]), "+f"(d[3])
        : "r"(a[0]), "r"(a[1]), "r"(a[2]), "r"(a[3]), "r"(b0), "r"(b1));
}

__device__ __forceinline__ void cpa16(uint32_t dst, const void* src) {
    asm volatile("cp.async.cg.shared.global [%0], [%1], 16;"
                 :: "r"(dst), "l"(src) : "memory");
}
#define CPA_COMMIT() asm volatile("cp.async.commit_group;" ::: "memory")
#define CPA_WAIT(n)  asm volatile("cp.async.wait_group %0;" :: "n"(n) : "memory")

// ---------------- pre-pass 1: K -> fp16 copy (skip fully-masked keys) --------
__global__ void kconv(const float* __restrict__ Kg, size_t n4,
                      const int* __restrict__ vlen, int Kn) {
    size_t i = (size_t)blockIdx.x * blockDim.x + threadIdx.x;
    if (i >= n4) return;
    // 32 float4 per key row (DD=128): key index and batch from linear index
    const int key = (int)((i >> 5) % (size_t)Kn);
    const int b   = (int)(i / ((size_t)Kn * 32));
    const int vr  = (vlen[b] + 63) & ~63;          // main kernel reads [0, vr)
    if (key >= vr) return;
    float4 v = ((const float4*)Kg)[i];
    __half2 h0 = __floats2half2_rn(v.x, v.y);
    __half2 h1 = __floats2half2_rn(v.z, v.w);
    ((uint2*)g_Kc)[i] = make_uint2(*(uint32_t*)&h0, *(uint32_t*)&h1);
}

// ---------------- pre-pass 2: V -> g_Vt[b][d][key] (skip masked blocks) ------
__global__ void vtrans(const float* __restrict__ Vg, int Kn,
                       const int* __restrict__ vlen) {
    __shared__ float tile[32][33];
    const int b  = blockIdx.z;
    const int k0 = blockIdx.x * 32;
    const int vr = (vlen[b] + 63) & ~63;
    if (k0 >= vr) return;                           // whole block masked
    const int d0 = blockIdx.y * 32;
    const int tx = threadIdx.x, ty = threadIdx.y;

    const float* src = Vg + ((size_t)b * Kn + k0) * DD + d0;
    #pragma unroll
    for (int j = 0; j < 4; j++)
        tile[ty + 8 * j][tx] = src[(size_t)(ty + 8 * j) * DD + tx];
    __syncthreads();

    __half* dst = g_Vt + ((size_t)b * DD + d0) * Kn + k0;
    #pragma unroll
    for (int j = 0; j < 4; j++)
        dst[(size_t)(ty + 8 * j) * Kn + tx] = __float2half_rn(tile[tx][ty + 8 * j]);
}

// ---------------- scheduler: parallel vlen load + LPT order ----------------
__global__ void sched(const int* __restrict__ vlen, int B) {
    __shared__ int vls[64];
    const int tid = threadIdx.x;
    if (tid < B) vls[tid] = vlen[tid];              // parallel, not serial
    __syncthreads();
    if (tid == 0) {
        int idx[64], vl[64];
        for (int i = 0; i < B; i++) { idx[i] = i; vl[i] = vls[i]; }
        for (int i = 1; i < B; i++) {               // insertion sort desc
            int vi = vl[i], ii = idx[i], j = i - 1;
            while (j >= 0 && vl[j] < vi) {
                vl[j + 1] = vl[j]; idx[j + 1] = idx[j]; j--;
            }
            vl[j + 1] = vi; idx[j + 1] = ii;
        }
        for (int i = 0; i < B; i++) g_order[i] = idx[i];
        g_next = 0;
    }
}

// ---------------- main fused attention (persistent, 3 CTAs/SM) ----------------
__global__ __launch_bounds__(NTH, 3)
void attn_mma(const float* __restrict__ Qg, const int* __restrict__ vlen,
              float* __restrict__ Og, int Qn, int Kn, int nq, int nunits)
{
    extern __shared__ uint32_t smem[];  // 2 x (K [64][136]h ++ V^T [128][72]h)
    const uint32_t sbase = smem_u32(smem);

    const int tid  = threadIdx.x;
    const int w    = tid >> 5;                  // 0..3
    const int lane = tid & 31;
    const int g    = lane >> 2;                 // row within m16 group
    const int t    = lane & 3;                  // thread-in-group
    const float scale = 0.088388347648318447f;  // 1/sqrt(128)
    const unsigned FULL = 0xFFFFFFFFu;

    // ldmatrix per-lane address pattern (shared by K and V^T tiles)
    const int rly = (lane & 7) + ((lane >> 4) & 1) * 8;   // row within 16-block
    const int cc  = (lane >> 3) & 1;                      // 16B chunk (8 halfs)
    const uint32_t kB0 = sbase + (uint32_t)(rly * KSTRB + cc * 16);
    const uint32_t vB0 = sbase + VOFFB + (uint32_t)(rly * VSTRB + cc * 16);

    // cp.async per-thread address components (loop-invariant)
    const int ldK_r = tid >> 4, ldK_c = (tid & 15) * 16;       // K rows 0..7(+8)
    const int ldV_d = tid >> 3, ldV_k = (tid & 7) * 16;        // V rows 0..15(+16)

    for (;;) {
        // ---- pop next work unit ----
        if (tid == 0) smem[WSLOT] = (uint32_t)atomicAdd(&g_next, 1);
        __syncthreads();
        const int u = (int)smem[WSLOT];
        if (u >= nunits) break;

        const int b     = g_order[u / nq];
        const int qb    = (u % nq) * BQ + w * 16;    // this warp's 16 q-rows
        const int valid = vlen[b];

        const __half* kcb = g_Kc + (size_t)b * Kn * DD;
        const __half* vtb = g_Vt + (size_t)b * DD * Kn;

        // ---- Q fragments in registers (scale folded, fp16 packed) ----
        uint32_t qf[8][4];
        {
            const float* q0 = Qg + ((size_t)b * Qn + qb + g) * DD;
            const float* q1 = Qg + ((size_t)b * Qn + qb + g + 8) * DD;
            #pragma unroll
            for (int c = 0; c < 8; c++) {
                const int d0 = c * 16 + 2 * t;
                float2 x0 = *(const float2*)(q0 + d0);
                float2 x1 = *(const float2*)(q1 + d0);
                float2 y0 = *(const float2*)(q0 + d0 + 8);
                float2 y1 = *(const float2*)(q1 + d0 + 8);
                __half2 h;
                h = __floats2half2_rn(x0.x * scale, x0.y * scale); qf[c][0] = *(uint32_t*)&h;
                h = __floats2half2_rn(x1.x * scale, x1.y * scale); qf[c][1] = *(uint32_t*)&h;
                h = __floats2half2_rn(y0.x * scale, y0.y * scale); qf[c][2] = *(uint32_t*)&h;
                h = __floats2half2_rn(y1.x * scale, y1.y * scale); qf[c][3] = *(uint32_t*)&h;
            }
        }

        float oacc[16][4];
        #pragma unroll
        for (int i = 0; i < 16; i++)
            { oacc[i][0] = oacc[i][1] = oacc[i][2] = oacc[i][3] = 0.f; }
        float lac0 = 0.f, lac1 = 0.f;

        const int ktiles = (valid + BK - 1) / BK;

        // loader: bb is a literal at every call site -> addresses const-fold
        auto load_tile = [&](int kt, uint32_t bb) {
            const int k0 = kt * BK;
            const __half* ksrc = kcb + (size_t)(k0 + ldK_r) * DD + (ldK_c >> 1);
            uint32_t kdst = sbase + bb + (uint32_t)(ldK_r * KSTRB + ldK_c);
            #pragma unroll
            for (int c = 0; c < 8; c++)            // 8 rows apart per step
                cpa16(kdst + (uint32_t)(c * 8 * KSTRB), ksrc + (size_t)(c * 8) * DD);
            const __half* vsrc = vtb + (size_t)ldV_d * Kn + k0 + (ldV_k >> 1);
            uint32_t vdst = sbase + bb + VOFFB + (uint32_t)(ldV_d * VSTRB + ldV_k);
            #pragma unroll
            for (int c = 0; c < 8; c++)            // 16 d-rows apart per step
                cpa16(vdst + (uint32_t)(c * 16 * VSTRB), vsrc + (size_t)(c * 16) * Kn);
        };

        // one tile step; boff/obff are literals at the two call sites
        auto step = [&](int kt, uint32_t boff, uint32_t obff) {
            const int k0 = kt * BK;
            if (kt + 1 < ktiles) {
                load_tile(kt + 1, obff);
                CPA_COMMIT();
                CPA_WAIT(1);
            } else {
                CPA_WAIT(0);
            }
            __syncthreads();

            // ---- GEMM1: S(16x64) = Q . K^T (fp16 m16n8k16) ----
            float sacc[8][4];
            #pragma unroll
            for (int i = 0; i < 8; i++)
                { sacc[i][0] = sacc[i][1] = sacc[i][2] = sacc[i][3] = 0.f; }

            #pragma unroll
            for (int c = 0; c < 8; c++) {            // k16 chunk over d
                #pragma unroll
                for (int ng = 0; ng < 4; ng++) {     // n16 group over keys
                    uint32_t kb[4];
                    ldsm4(kb, kB0 + boff + (uint32_t)(ng * 16 * KSTRB + c * 32));
                    mma16h(sacc[2 * ng],     qf[c], kb[0], kb[1]);
                    mma16h(sacc[2 * ng + 1], qf[c], kb[2], kb[3]);
                }
            }

            // ---- mask + exp + row-sums; pack P to fp16 (== A-frag layout) ----
            uint32_t ph[8][2];
            #pragma unroll
            for (int nb = 0; nb < 8; nb++) {
                const int c0 = k0 + nb * 8 + 2 * t;
                const bool m0 = c0 < valid, m1 = (c0 + 1) < valid;
                float p0 = m0 ? __expf(sacc[nb][0]) : 0.f;
                float p1 = m1 ? __expf(sacc[nb][1]) : 0.f;
                float p2 = m0 ? __expf(sacc[nb][2]) : 0.f;
                float p3 = m1 ? __expf(sacc[nb][3]) : 0.f;
                lac0 += p0 + p1;  lac1 += p2 + p3;
                __half2 h0 = __floats2half2_rn(p0, p1);
                __half2 h1 = __floats2half2_rn(p2, p3);
                ph[nb][0] = *(uint32_t*)&h0;
                ph[nb][1] = *(uint32_t*)&h1;
            }

            // ---- GEMM2: O(16x128) += P . V (fp16, no shuffles) ----
            #pragma unroll
            for (int i = 0; i < 4; i++) {            // k16 chunk over 64 keys
                uint32_t a[4];
                a[0] = ph[2 * i][0];
                a[1] = ph[2 * i][1];
                a[2] = ph[2 * i + 1][0];
                a[3] = ph[2 * i + 1][1];
                #pragma unroll
                for (int nbp = 0; nbp < 8; nbp++) {  // n16 block over d
                    uint32_t vb[4];
                    ldsm4(vb, vB0 + boff + (uint32_t)(nbp * 16 * VSTRB + i * 32));
                    mma16h(oacc[2 * nbp],     a, vb[0], vb[1]);
                    mma16h(oacc[2 * nbp + 1], a, vb[2], vb[3]);
                }
            }

            __syncthreads();    // buffer reusable before next-next cp.async
        };

        load_tile(0, 0u);
        CPA_COMMIT();

        for (int kt = 0; kt < ktiles; kt += 2) {
            step(kt, 0u, (uint32_t)BUFB);                     // buffer 0
            if (kt + 1 < ktiles)
                step(kt + 1, (uint32_t)BUFB, 0u);             // buffer 1
        }

        // ---- epilogue: reduce row sums in quad, normalize, store ----
        float l0 = lac0, l1 = lac1;
        l0 += __shfl_xor_sync(FULL, l0, 1);
        l0 += __shfl_xor_sync(FULL, l0, 2);
        l1 += __shfl_xor_sync(FULL, l1, 1);
        l1 += __shfl_xor_sync(FULL, l1, 2);
        const float inv0 = 1.0f / l0;
        const float inv1 = 1.0f / l1;

        float2* o0 = (float2*)(Og + ((size_t)b * Qn + qb + g) * DD);
        float2* o1 = (float2*)(Og + ((size_t)b * Qn + qb + g + 8) * DD);
        #pragma unroll
        for (int nb = 0; nb < 16; nb++) {
            o0[nb * 4 + t] = make_float2(oacc[nb][0] * inv0, oacc[nb][1] * inv0);
            o1[nb * 4 + t] = make_float2(oacc[nb][2] * inv1, oacc[nb][3] * inv1);
        }
    }
}

extern "C" void kernel_launch(void* const* d_in, const int* in_sizes, int n_in,
                              void* d_out, int out_size)
{
    const float* Q  = (const float*)d_in[0];
    const float* K  = (const float*)d_in[1];
    const float* V  = (const float*)d_in[2];
    const int*   vl = (const int*)d_in[3];

    const int B  = in_sizes[3];
    const int Qn = in_sizes[0] / (B * DD);
    const int Kn = in_sizes[1] / (B * DD);
    const int nq = Qn / BQ;
    const int nunits = B * nq;

    const size_t n4 = (size_t)B * Kn * DD / 4;
    kconv<<<(unsigned)((n4 + 255) / 256), 256>>>(K, n4, vl, Kn);

    dim3 tg(Kn / 32, DD / 32, B);
    vtrans<<<tg, dim3(32, 8)>>>(V, Kn, vl);

    sched<<<1, 32>>>(vl, B);

    int dev = 0, nsm = 148;
    cudaGetDevice(&dev);
    cudaDeviceGetAttribute(&nsm, cudaDevAttrMultiProcessorCount, dev);
    int grid = 3 * nsm;
    if (grid > nunits) grid = nunits;

    cudaFuncSetAttribute(attn_mma, cudaFuncAttributeMaxDynamicSharedMemorySize,
                         SMEMB);
    attn_mma<<<grid, NTH, SMEMB>>>(Q, vl, (float*)d_out, Qn, Kn, nq, nunits);
}